// round 1
// baseline (speedup 1.0000x reference)
#include <cuda_runtime.h>
#include <math.h>

#define D 64
#define V_MAX 100000

// ---------------- scratch (__device__ globals: no allocation allowed) -------
__device__ float g_eL[V_MAX];          // local node scores
__device__ float g_eG[V_MAX];          // global node scores
__device__ float g_denL[V_MAX];        // softmax denominators
__device__ float g_denG[V_MAX];
__device__ float g_cI[V_MAX];          // mean counts
__device__ float g_cS[V_MAX];
__device__ float g_Np[V_MAX * D];      // global-GAT weighted sum
__device__ float g_YI[V_MAX * D];      // int-edge sum
__device__ float g_YS[V_MAX * D];      // sim-edge sum

// ---------------- zero accumulators + output --------------------------------
__global__ void zero_kernel(float* __restrict__ out, int V) {
    int i = blockIdx.x * blockDim.x + threadIdx.x;
    int nOut = V * 128;
    if (i < nOut) out[i] = 0.0f;
    int nD = V * D;
    if (i < nD) { g_Np[i] = 0.0f; g_YI[i] = 0.0f; g_YS[i] = 0.0f; }
    if (i < V)  { g_denL[i] = 0.0f; g_denG[i] = 0.0f; g_cI[i] = 0.0f; g_cS[i] = 0.0f; }
}

// ---------------- node scores: e = tanh(N @ W1) @ w2  (local & global) ------
__global__ __launch_bounds__(256) void scores_kernel(
    const float* __restrict__ localN, const float* __restrict__ globalN,
    const float* __restrict__ lW1, const float* __restrict__ lw2,
    const float* __restrict__ gW1, const float* __restrict__ gw2, int V)
{
    __shared__ float sWl[D * D];
    __shared__ float sWg[D * D];
    __shared__ float swl[D];
    __shared__ float swg[D];
    for (int i = threadIdx.x; i < D * D; i += blockDim.x) { sWl[i] = lW1[i]; sWg[i] = gW1[i]; }
    for (int i = threadIdx.x; i < D; i += blockDim.x)     { swl[i] = lw2[i]; swg[i] = gw2[i]; }
    __syncthreads();

    int warp   = (blockIdx.x * blockDim.x + threadIdx.x) >> 5;
    int lane   = threadIdx.x & 31;
    int nwarps = (gridDim.x * blockDim.x) >> 5;

    for (int v = warp; v < V; v += nwarps) {
        // ---- local graph score ----
        {
            float n0 = localN[v * D + lane];
            float n1 = localN[v * D + 32 + lane];
            float a0 = 0.f, a1 = 0.f;
            #pragma unroll
            for (int k = 0; k < 32; k++) {
                float nk = __shfl_sync(0xffffffffu, n0, k);
                a0 += nk * sWl[k * D + lane];
                a1 += nk * sWl[k * D + 32 + lane];
            }
            #pragma unroll
            for (int k = 0; k < 32; k++) {
                float nk = __shfl_sync(0xffffffffu, n1, k);
                a0 += nk * sWl[(k + 32) * D + lane];
                a1 += nk * sWl[(k + 32) * D + 32 + lane];
            }
            float e = tanhf(a0) * swl[lane] + tanhf(a1) * swl[32 + lane];
            #pragma unroll
            for (int o = 16; o > 0; o >>= 1) e += __shfl_xor_sync(0xffffffffu, e, o);
            if (lane == 0) g_eL[v] = e;
        }
        // ---- global graph score ----
        {
            float n0 = globalN[v * D + lane];
            float n1 = globalN[v * D + 32 + lane];
            float a0 = 0.f, a1 = 0.f;
            #pragma unroll
            for (int k = 0; k < 32; k++) {
                float nk = __shfl_sync(0xffffffffu, n0, k);
                a0 += nk * sWg[k * D + lane];
                a1 += nk * sWg[k * D + 32 + lane];
            }
            #pragma unroll
            for (int k = 0; k < 32; k++) {
                float nk = __shfl_sync(0xffffffffu, n1, k);
                a0 += nk * sWg[(k + 32) * D + lane];
                a1 += nk * sWg[(k + 32) * D + 32 + lane];
            }
            float e = tanhf(a0) * swg[lane] + tanhf(a1) * swg[32 + lane];
            #pragma unroll
            for (int o = 16; o > 0; o >>= 1) e += __shfl_xor_sync(0xffffffffu, e, o);
            if (lane == 0) g_eG[v] = e;
        }
    }
}

__device__ __forceinline__ void red_add_v4(float* p, float x, float y, float z, float w) {
    asm volatile("red.global.add.v4.f32 [%0], {%1,%2,%3,%4};"
                 :: "l"(p), "f"(x), "f"(y), "f"(z), "f"(w) : "memory");
}

// ---------------- GAT edge pass (softmax shift dropped: w = exp(e[src])) ----
// 16 lanes per edge; each lane handles one float4 of the 64-wide feature row.
__global__ __launch_bounds__(256) void gat_edge_kernel(
    const int* __restrict__ src, const int* __restrict__ dst, int E,
    const float* __restrict__ escore, const float* __restrict__ N,
    float* __restrict__ outsum, int rowstride,   // in floats
    float* __restrict__ denom)
{
    int t = blockIdx.x * blockDim.x + threadIdx.x;
    int g = t >> 4;
    int l = t & 15;
    if (g >= E) return;
    int s = src[g];
    int d = dst[g];
    float w = expf(escore[s]);
    const float4 x = reinterpret_cast<const float4*>(N + (size_t)s * D)[l];
    float* p = outsum + (size_t)d * rowstride + l * 4;
    red_add_v4(p, w * x.x, w * x.y, w * x.z, w * x.w);
    if (l == 0) atomicAdd(denom + d, w);
}

// ---------------- edge-mean pass: Y[dst] += E_row, cnt[dst] += 1 ------------
__global__ __launch_bounds__(256) void mean_edge_kernel(
    const int* __restrict__ dst, int E,
    const float* __restrict__ Edata,   // pre-offset
    float* __restrict__ Ysum, float* __restrict__ cnt)
{
    int t = blockIdx.x * blockDim.x + threadIdx.x;
    int g = t >> 4;
    int l = t & 15;
    if (g >= E) return;
    int d = dst[g];
    const float4 x = reinterpret_cast<const float4*>(Edata + (size_t)g * D)[l];
    float* p = Ysum + (size_t)d * D + l * 4;
    red_add_v4(p, x.x, x.y, x.z, x.w);
    if (l == 0) atomicAdd(cnt + d, 1.0f);
}

// ---------------- finalize: normalize, edge-GAT attention, S, write H -------
__global__ __launch_bounds__(256) void finalize_kernel(
    float* __restrict__ out, const float* __restrict__ Ws,
    const float* __restrict__ eW1, const float* __restrict__ ew2,
    const float* __restrict__ eW3, int V)
{
    __shared__ float sW1[D * D];
    __shared__ float sW3[D * D];
    __shared__ float sw2[D];
    for (int i = threadIdx.x; i < D * D; i += blockDim.x) { sW1[i] = eW1[i]; sW3[i] = eW3[i]; }
    for (int i = threadIdx.x; i < D; i += blockDim.x)     { sw2[i] = ew2[i]; }
    __syncthreads();

    int warp   = (blockIdx.x * blockDim.x + threadIdx.x) >> 5;
    int lane   = threadIdx.x & 31;
    int nwarps = (gridDim.x * blockDim.x) >> 5;

    for (int v = warp; v < V; v += nwarps) {
        // local GAT normalization directly in out[:, 0:64]
        float dl = g_denL[v];
        float il = dl > 0.f ? 1.f / dl : 1.f;
        out[v * 128 + lane]      *= il;
        out[v * 128 + 32 + lane] *= il;

        float dg = g_denG[v];
        float ig = dg > 0.f ? 1.f / dg : 1.f;
        float np0 = g_Np[v * D + lane]      * ig;
        float np1 = g_Np[v * D + 32 + lane] * ig;

        float ci = g_cI[v]; float ici = ci > 0.f ? 1.f / ci : 1.f;
        float cs = g_cS[v]; float ics = cs > 0.f ? 1.f / cs : 1.f;
        float yi0 = g_YI[v * D + lane]      * ici;
        float yi1 = g_YI[v * D + 32 + lane] * ici;
        float ys0 = g_YS[v * D + lane]      * ics;
        float ys1 = g_YS[v * D + 32 + lane] * ics;

        // tI = tanh(YI@eW1), tS = tanh(YS@eW1); eI = tI.ew2, eS = tS.ew2
        float a0 = 0.f, a1 = 0.f, b0 = 0.f, b1 = 0.f;
        #pragma unroll
        for (int k = 0; k < 32; k++) {
            float yik = __shfl_sync(0xffffffffu, yi0, k);
            float ysk = __shfl_sync(0xffffffffu, ys0, k);
            float w0 = sW1[k * D + lane], w1 = sW1[k * D + 32 + lane];
            a0 += yik * w0; a1 += yik * w1;
            b0 += ysk * w0; b1 += ysk * w1;
        }
        #pragma unroll
        for (int k = 0; k < 32; k++) {
            float yik = __shfl_sync(0xffffffffu, yi1, k);
            float ysk = __shfl_sync(0xffffffffu, ys1, k);
            float w0 = sW1[(32 + k) * D + lane], w1 = sW1[(32 + k) * D + 32 + lane];
            a0 += yik * w0; a1 += yik * w1;
            b0 += ysk * w0; b1 += ysk * w1;
        }
        float eI = tanhf(a0) * sw2[lane] + tanhf(a1) * sw2[32 + lane];
        float eS = tanhf(b0) * sw2[lane] + tanhf(b1) * sw2[32 + lane];
        #pragma unroll
        for (int o = 16; o > 0; o >>= 1) {
            eI += __shfl_xor_sync(0xffffffffu, eI, o);
            eS += __shfl_xor_sync(0xffffffffu, eS, o);
        }
        float mx = fmaxf(eI, eS);
        float u0 = expf(eI - mx), u1 = expf(eS - mx);
        float inv = 1.f / (u0 + u1);
        float A0 = u0 * inv, A1 = u1 * inv;

        float oy0 = A0 * yi0 + A1 * ys0;
        float oy1 = A0 * yi1 + A1 * ys1;

        // Fg = OY @ eW3
        float f0 = 0.f, f1 = 0.f;
        #pragma unroll
        for (int k = 0; k < 32; k++) {
            float ok = __shfl_sync(0xffffffffu, oy0, k);
            f0 += ok * sW3[k * D + lane];
            f1 += ok * sW3[k * D + 32 + lane];
        }
        #pragma unroll
        for (int k = 0; k < 32; k++) {
            float ok = __shfl_sync(0xffffffffu, oy1, k);
            f0 += ok * sW3[(32 + k) * D + lane];
            f1 += ok * sW3[(32 + k) * D + 32 + lane];
        }
        float s0 = Ws[v * D + lane]      * f0 + np0;
        float s1 = Ws[v * D + 32 + lane] * f1 + np1;
        out[v * 128 + 64 + lane] = s0;
        out[v * 128 + 96 + lane] = s1;
    }
}

// ---------------- launch ----------------------------------------------------
extern "C" void kernel_launch(void* const* d_in, const int* in_sizes, int n_in,
                              void* d_out, int out_size)
{
    const float* local_N  = (const float*)d_in[0];
    const float* global_N = (const float*)d_in[1];
    const float* edge_E   = (const float*)d_in[2];
    const float* Ws       = (const float*)d_in[3];
    const float* lW1      = (const float*)d_in[4];
    const float* lw2      = (const float*)d_in[5];
    const float* gW1      = (const float*)d_in[6];
    const float* gw2      = (const float*)d_in[7];
    const float* eW1      = (const float*)d_in[8];
    const float* ew2      = (const float*)d_in[9];
    const float* eW3      = (const float*)d_in[10];
    const int* ng_src     = (const int*)d_in[11];
    const int* ng_dst     = (const int*)d_in[12];
    const int* local_src  = (const int*)d_in[13];
    const int* local_dst  = (const int*)d_in[14];
    const int* int_src    = (const int*)d_in[15];  (void)int_src;
    const int* int_dst    = (const int*)d_in[16];
    const int* sim_src    = (const int*)d_in[17];  (void)sim_src;
    const int* sim_dst    = (const int*)d_in[18];

    const int V      = in_sizes[0] / D;
    const int E_NG   = in_sizes[11];
    const int E_LOC  = in_sizes[13];
    const int E_INT  = in_sizes[15];
    const int E_SIM  = in_sizes[17];

    float* out = (float*)d_out;

    // K0: zero out + accumulators
    {
        int n = V * 128;
        zero_kernel<<<(n + 255) / 256, 256>>>(out, V);
    }

    // K1: node scores (local + global)
    scores_kernel<<<(V + 7) / 8, 256>>>(local_N, global_N, lW1, lw2, gW1, gw2, V);

    // K2: GAT edge passes. local -> out[:,0:64] (stride 128); ng -> g_Np (stride 64)
    {
        float* pNp;   cudaGetSymbolAddress((void**)&pNp,   g_Np);
        float* pDenL; cudaGetSymbolAddress((void**)&pDenL, g_denL);
        float* pDenG; cudaGetSymbolAddress((void**)&pDenG, g_denG);
        float* pYI;   cudaGetSymbolAddress((void**)&pYI,   g_YI);
        float* pYS;   cudaGetSymbolAddress((void**)&pYS,   g_YS);
        float* pEL;   cudaGetSymbolAddress((void**)&pEL,   g_eL);
        float* pEG;   cudaGetSymbolAddress((void**)&pEG,   g_eG);
        float* pCI;   cudaGetSymbolAddress((void**)&pCI,   g_cI);
        float* pCS;   cudaGetSymbolAddress((void**)&pCS,   g_cS);

        {
            long threads = (long)E_LOC * 16;
            gat_edge_kernel<<<(int)((threads + 255) / 256), 256>>>(
                local_src, local_dst, E_LOC, pEL, local_N, out, 128, pDenL);
        }
        {
            long threads = (long)E_NG * 16;
            gat_edge_kernel<<<(int)((threads + 255) / 256), 256>>>(
                ng_src, ng_dst, E_NG, pEG, global_N, pNp, 64, pDenG);
        }

        // K3: edge-mean passes
        {
            long threads = (long)E_INT * 16;
            mean_edge_kernel<<<(int)((threads + 255) / 256), 256>>>(
                int_dst, E_INT, edge_E, pYI, pCI);
        }
        {
            long threads = (long)E_SIM * 16;
            mean_edge_kernel<<<(int)((threads + 255) / 256), 256>>>(
                sim_dst, E_SIM, edge_E + (size_t)E_INT * D, pYS, pCS);
        }
    }

    // K4: finalize
    finalize_kernel<<<(V + 7) / 8, 256>>>(out, Ws, eW1, ew2, eW3, V);
}

// round 2
// speedup vs baseline: 1.2019x; 1.2019x over previous
#include <cuda_runtime.h>
#include <math.h>

#define D 64
#define V_MAX 100000

// ---------------- scratch (__device__ globals) -------------------------------
__device__ float g_wL[V_MAX];            // exp(local score)
__device__ float g_wG[V_MAX];            // exp(global score)
__device__ float g_WNL[V_MAX * D];       // exp(eL[v]) * localN[v]
__device__ float g_WNG[V_MAX * D];       // exp(eG[v]) * globalN[v]
__device__ float g_accL[V_MAX * D];      // local GAT weighted sum
__device__ float g_accG[V_MAX * D];      // global GAT weighted sum
__device__ float g_denL[V_MAX];
__device__ float g_denG[V_MAX];
__device__ float g_YI[V_MAX * D];
__device__ float g_YS[V_MAX * D];
__device__ float g_cI[V_MAX];
__device__ float g_cS[V_MAX];

// ---------------- zero accumulators -----------------------------------------
__global__ void zero_kernel(int V) {
    int i = blockIdx.x * blockDim.x + threadIdx.x;
    float4 z = make_float4(0.f, 0.f, 0.f, 0.f);
    int n4 = V * (D / 4);
    if (i < n4) {
        reinterpret_cast<float4*>(g_accL)[i] = z;
        reinterpret_cast<float4*>(g_accG)[i] = z;
        reinterpret_cast<float4*>(g_YI)[i]   = z;
        reinterpret_cast<float4*>(g_YS)[i]   = z;
    }
    if (i < V) { g_denL[i] = 0.f; g_denG[i] = 0.f; g_cI[i] = 0.f; g_cS[i] = 0.f; }
}

// ---------------- scores + pre-scale: w=exp(tanh(N@W1)@w2), WN = w*N ---------
// 4 nodes per warp: weight LDS amortized 4x.
__device__ __forceinline__ void score_scale_4nodes(
    const float* __restrict__ N, const float* __restrict__ sW,
    const float* __restrict__ sw2, float* __restrict__ wOut,
    float* __restrict__ WN, int base, int V, int lane)
{
    float n0[4], n1[4];
    #pragma unroll
    for (int i = 0; i < 4; i++) {
        int v = (base + i < V) ? base + i : V - 1;
        n0[i] = N[v * D + lane];
        n1[i] = N[v * D + 32 + lane];
    }
    float a0[4] = {0.f,0.f,0.f,0.f}, a1[4] = {0.f,0.f,0.f,0.f};
    #pragma unroll
    for (int k = 0; k < 32; k++) {
        float w0 = sW[k * D + lane], w1 = sW[k * D + 32 + lane];
        #pragma unroll
        for (int i = 0; i < 4; i++) {
            float nk = __shfl_sync(0xffffffffu, n0[i], k);
            a0[i] += nk * w0; a1[i] += nk * w1;
        }
    }
    #pragma unroll
    for (int k = 0; k < 32; k++) {
        float w0 = sW[(k + 32) * D + lane], w1 = sW[(k + 32) * D + 32 + lane];
        #pragma unroll
        for (int i = 0; i < 4; i++) {
            float nk = __shfl_sync(0xffffffffu, n1[i], k);
            a0[i] += nk * w0; a1[i] += nk * w1;
        }
    }
    #pragma unroll
    for (int i = 0; i < 4; i++) {
        float e = tanhf(a0[i]) * sw2[lane] + tanhf(a1[i]) * sw2[32 + lane];
        #pragma unroll
        for (int o = 16; o > 0; o >>= 1) e += __shfl_xor_sync(0xffffffffu, e, o);
        float w = expf(e);
        int v = base + i;
        if (v < V) {
            if (lane == 0) wOut[v] = w;
            WN[v * D + lane]      = w * n0[i];
            WN[v * D + 32 + lane] = w * n1[i];
        }
    }
}

__global__ __launch_bounds__(256) void scores_kernel(
    const float* __restrict__ localN, const float* __restrict__ globalN,
    const float* __restrict__ lW1, const float* __restrict__ lw2,
    const float* __restrict__ gW1, const float* __restrict__ gw2, int V)
{
    __shared__ float sWl[D * D];
    __shared__ float sWg[D * D];
    __shared__ float swl[D];
    __shared__ float swg[D];
    for (int i = threadIdx.x; i < D * D; i += blockDim.x) { sWl[i] = lW1[i]; sWg[i] = gW1[i]; }
    for (int i = threadIdx.x; i < D; i += blockDim.x)     { swl[i] = lw2[i]; swg[i] = gw2[i]; }
    __syncthreads();

    int lane = threadIdx.x & 31;
    int grp  = (blockIdx.x * blockDim.x + threadIdx.x) >> 5;
    int ngrp = (gridDim.x * blockDim.x) >> 5;

    for (int base = grp * 4; base < V; base += ngrp * 4) {
        score_scale_4nodes(localN,  sWl, swl, g_wL, g_WNL, base, V, lane);
        score_scale_4nodes(globalN, sWg, swg, g_wG, g_WNG, base, V, lane);
    }
}

__device__ __forceinline__ void red_add_v4(float* p, float x, float y, float z, float w) {
    asm volatile("red.global.add.v4.f32 [%0], {%1,%2,%3,%4};"
                 :: "l"(p), "f"(x), "f"(y), "f"(z), "f"(w) : "memory");
}

// ---------------- GAT edge pass: pure gather + RED ---------------------------
__global__ __launch_bounds__(256) void gat_edge_kernel(
    const int* __restrict__ src, const int* __restrict__ dst, int E,
    const float* __restrict__ WN, const float* __restrict__ w,
    float* __restrict__ acc, float* __restrict__ denom)
{
    int t = blockIdx.x * blockDim.x + threadIdx.x;
    int g = t >> 4;
    int l = t & 15;
    if (g >= E) return;
    int s = src[g];
    int d = dst[g];
    const float4 x = reinterpret_cast<const float4*>(WN + (size_t)s * D)[l];
    red_add_v4(acc + (size_t)d * D + l * 4, x.x, x.y, x.z, x.w);
    if (l == 0) atomicAdd(denom + d, w[s]);
}

// ---------------- edge-mean pass ---------------------------------------------
__global__ __launch_bounds__(256) void mean_edge_kernel(
    const int* __restrict__ dst, int E,
    const float* __restrict__ Edata,   // pre-offset
    float* __restrict__ Ysum, float* __restrict__ cnt)
{
    int t = blockIdx.x * blockDim.x + threadIdx.x;
    int g = t >> 4;
    int l = t & 15;
    if (g >= E) return;
    int d = dst[g];
    const float4 x = reinterpret_cast<const float4*>(Edata + (size_t)g * D)[l];
    red_add_v4(Ysum + (size_t)d * D + l * 4, x.x, x.y, x.z, x.w);
    if (l == 0) atomicAdd(cnt + d, 1.0f);
}

// ---------------- finalize: 2 nodes per warp ---------------------------------
__global__ __launch_bounds__(256) void finalize_kernel(
    float* __restrict__ out, const float* __restrict__ Ws,
    const float* __restrict__ eW1, const float* __restrict__ ew2,
    const float* __restrict__ eW3, int V)
{
    __shared__ float sW1[D * D];
    __shared__ float sW3[D * D];
    __shared__ float sw2[D];
    for (int i = threadIdx.x; i < D * D; i += blockDim.x) { sW1[i] = eW1[i]; sW3[i] = eW3[i]; }
    for (int i = threadIdx.x; i < D; i += blockDim.x)     { sw2[i] = ew2[i]; }
    __syncthreads();

    int lane = threadIdx.x & 31;
    int grp  = (blockIdx.x * blockDim.x + threadIdx.x) >> 5;
    int ngrp = (gridDim.x * blockDim.x) >> 5;

    for (int base = grp * 2; base < V; base += ngrp * 2) {
        float yi0[2], yi1[2], ys0[2], ys1[2];
        #pragma unroll
        for (int i = 0; i < 2; i++) {
            int v = (base + i < V) ? base + i : V - 1;
            float ci = g_cI[v]; float ici = ci > 0.f ? 1.f / ci : 1.f;
            float cs = g_cS[v]; float ics = cs > 0.f ? 1.f / cs : 1.f;
            yi0[i] = g_YI[v * D + lane]      * ici;
            yi1[i] = g_YI[v * D + 32 + lane] * ici;
            ys0[i] = g_YS[v * D + lane]      * ics;
            ys1[i] = g_YS[v * D + 32 + lane] * ics;
        }

        float a0[2] = {0.f,0.f}, a1[2] = {0.f,0.f};
        float b0[2] = {0.f,0.f}, b1[2] = {0.f,0.f};
        #pragma unroll
        for (int k = 0; k < 32; k++) {
            float w0 = sW1[k * D + lane], w1 = sW1[k * D + 32 + lane];
            #pragma unroll
            for (int i = 0; i < 2; i++) {
                float yik = __shfl_sync(0xffffffffu, yi0[i], k);
                float ysk = __shfl_sync(0xffffffffu, ys0[i], k);
                a0[i] += yik * w0; a1[i] += yik * w1;
                b0[i] += ysk * w0; b1[i] += ysk * w1;
            }
        }
        #pragma unroll
        for (int k = 0; k < 32; k++) {
            float w0 = sW1[(32 + k) * D + lane], w1 = sW1[(32 + k) * D + 32 + lane];
            #pragma unroll
            for (int i = 0; i < 2; i++) {
                float yik = __shfl_sync(0xffffffffu, yi1[i], k);
                float ysk = __shfl_sync(0xffffffffu, ys1[i], k);
                a0[i] += yik * w0; a1[i] += yik * w1;
                b0[i] += ysk * w0; b1[i] += ysk * w1;
            }
        }

        float oy0[2], oy1[2];
        #pragma unroll
        for (int i = 0; i < 2; i++) {
            float eI = tanhf(a0[i]) * sw2[lane] + tanhf(a1[i]) * sw2[32 + lane];
            float eS = tanhf(b0[i]) * sw2[lane] + tanhf(b1[i]) * sw2[32 + lane];
            #pragma unroll
            for (int o = 16; o > 0; o >>= 1) {
                eI += __shfl_xor_sync(0xffffffffu, eI, o);
                eS += __shfl_xor_sync(0xffffffffu, eS, o);
            }
            float mx = fmaxf(eI, eS);
            float u0 = expf(eI - mx), u1 = expf(eS - mx);
            float inv = 1.f / (u0 + u1);
            oy0[i] = u0 * inv * yi0[i] + u1 * inv * ys0[i];
            oy1[i] = u0 * inv * yi1[i] + u1 * inv * ys1[i];
        }

        float f0[2] = {0.f,0.f}, f1[2] = {0.f,0.f};
        #pragma unroll
        for (int k = 0; k < 32; k++) {
            float w0 = sW3[k * D + lane], w1 = sW3[k * D + 32 + lane];
            #pragma unroll
            for (int i = 0; i < 2; i++) {
                float ok = __shfl_sync(0xffffffffu, oy0[i], k);
                f0[i] += ok * w0; f1[i] += ok * w1;
            }
        }
        #pragma unroll
        for (int k = 0; k < 32; k++) {
            float w0 = sW3[(32 + k) * D + lane], w1 = sW3[(32 + k) * D + 32 + lane];
            #pragma unroll
            for (int i = 0; i < 2; i++) {
                float ok = __shfl_sync(0xffffffffu, oy1[i], k);
                f0[i] += ok * w0; f1[i] += ok * w1;
            }
        }

        #pragma unroll
        for (int i = 0; i < 2; i++) {
            int v = base + i;
            if (v >= V) break;
            // local GAT -> out[:, 0:64]
            float dl = g_denL[v]; float il = dl > 0.f ? 1.f / dl : 1.f;
            out[v * 128 + lane]      = g_accL[v * D + lane]      * il;
            out[v * 128 + 32 + lane] = g_accL[v * D + 32 + lane] * il;
            // S = Ws * Fg + Np -> out[:, 64:128]
            float dg = g_denG[v]; float ig = dg > 0.f ? 1.f / dg : 1.f;
            float np0 = g_accG[v * D + lane]      * ig;
            float np1 = g_accG[v * D + 32 + lane] * ig;
            out[v * 128 + 64 + lane] = Ws[v * D + lane]      * f0[i] + np0;
            out[v * 128 + 96 + lane] = Ws[v * D + 32 + lane] * f1[i] + np1;
        }
    }
}

// ---------------- launch ------------------------------------------------------
extern "C" void kernel_launch(void* const* d_in, const int* in_sizes, int n_in,
                              void* d_out, int out_size)
{
    const float* local_N  = (const float*)d_in[0];
    const float* global_N = (const float*)d_in[1];
    const float* edge_E   = (const float*)d_in[2];
    const float* Ws       = (const float*)d_in[3];
    const float* lW1      = (const float*)d_in[4];
    const float* lw2      = (const float*)d_in[5];
    const float* gW1      = (const float*)d_in[6];
    const float* gw2      = (const float*)d_in[7];
    const float* eW1      = (const float*)d_in[8];
    const float* ew2      = (const float*)d_in[9];
    const float* eW3      = (const float*)d_in[10];
    const int* ng_src     = (const int*)d_in[11];
    const int* ng_dst     = (const int*)d_in[12];
    const int* local_src  = (const int*)d_in[13];
    const int* local_dst  = (const int*)d_in[14];
    const int* int_dst    = (const int*)d_in[16];
    const int* sim_dst    = (const int*)d_in[18];

    const int V      = in_sizes[0] / D;
    const int E_NG   = in_sizes[11];
    const int E_LOC  = in_sizes[13];
    const int E_INT  = in_sizes[15];
    const int E_SIM  = in_sizes[17];

    float* out = (float*)d_out;

    float *pWL, *pWG, *pWNL, *pWNG, *pAL, *pAG, *pDL, *pDG, *pYI, *pYS, *pCI, *pCS;
    cudaGetSymbolAddress((void**)&pWL,  g_wL);
    cudaGetSymbolAddress((void**)&pWG,  g_wG);
    cudaGetSymbolAddress((void**)&pWNL, g_WNL);
    cudaGetSymbolAddress((void**)&pWNG, g_WNG);
    cudaGetSymbolAddress((void**)&pAL,  g_accL);
    cudaGetSymbolAddress((void**)&pAG,  g_accG);
    cudaGetSymbolAddress((void**)&pDL,  g_denL);
    cudaGetSymbolAddress((void**)&pDG,  g_denG);
    cudaGetSymbolAddress((void**)&pYI,  g_YI);
    cudaGetSymbolAddress((void**)&pYS,  g_YS);
    cudaGetSymbolAddress((void**)&pCI,  g_cI);
    cudaGetSymbolAddress((void**)&pCS,  g_cS);

    // K0: zero accumulators (V*16 float4 stores)
    zero_kernel<<<(V * 16 + 255) / 256, 256>>>(V);

    // K1: node scores + pre-scaled rows
    scores_kernel<<<(V / 4 + 7) / 8, 256>>>(local_N, global_N, lW1, lw2, gW1, gw2, V);

    // K2: GAT edge passes
    {
        long t1 = (long)E_LOC * 16;
        gat_edge_kernel<<<(int)((t1 + 255) / 256), 256>>>(
            local_src, local_dst, E_LOC, pWNL, pWL, pAL, pDL);
        long t2 = (long)E_NG * 16;
        gat_edge_kernel<<<(int)((t2 + 255) / 256), 256>>>(
            ng_src, ng_dst, E_NG, pWNG, pWG, pAG, pDG);
    }

    // K3: edge-mean passes
    {
        long t3 = (long)E_INT * 16;
        mean_edge_kernel<<<(int)((t3 + 255) / 256), 256>>>(int_dst, E_INT, edge_E, pYI, pCI);
        long t4 = (long)E_SIM * 16;
        mean_edge_kernel<<<(int)((t4 + 255) / 256), 256>>>(
            sim_dst, E_SIM, edge_E + (size_t)E_INT * D, pYS, pCS);
    }

    // K4: finalize
    finalize_kernel<<<(V / 2 + 7) / 8, 256>>>(out, Ws, eW1, ew2, eW3, V);
}

// round 3
// speedup vs baseline: 1.3458x; 1.1197x over previous
#include <cuda_runtime.h>
#include <math.h>

#define D 64
#define V_MAX 100000
#define NBMAX 128                 // scan blocks per graph (128*1024 >= V_MAX)
#define E_NG_MAX  2000000
#define E_LOC_MAX 1000000
#define E_INT_MAX 1200000
#define E_SIM_MAX  800000

// ---------------- scratch (__device__ globals) -------------------------------
__device__ float g_wL[V_MAX];
__device__ float g_wG[V_MAX];
__device__ float g_WNL[V_MAX * D];
__device__ float g_WNG[V_MAX * D];
__device__ float g_Np[V_MAX * D];     // normalized global GAT output
__device__ float g_YI[V_MAX * D];     // normalized int-edge mean
__device__ float g_YS[V_MAX * D];     // normalized sim-edge mean

__device__ int g_cnt[4 * V_MAX];
__device__ int g_off[4 * (V_MAX + 1)];
__device__ int g_cur[4 * V_MAX];
__device__ int g_bsum[4 * NBMAX];
__device__ int g_binNG[E_NG_MAX];
__device__ int g_binLOC[E_LOC_MAX];
__device__ int g_binI[E_INT_MAX];
__device__ int g_binS[E_SIM_MAX];

// ---------------- zero counts ------------------------------------------------
__global__ void zero_cnt_kernel() {
    int i = blockIdx.x * blockDim.x + threadIdx.x;
    if (i < 4 * V_MAX) g_cnt[i] = 0;
}

// ---------------- histogram ---------------------------------------------------
__global__ __launch_bounds__(256) void count_kernel(const int* __restrict__ dst, int E, int g) {
    int i = blockIdx.x * blockDim.x + threadIdx.x;
    if (i < E) atomicAdd(&g_cnt[g * V_MAX + dst[i]], 1);
}

// ---------------- scan helpers ------------------------------------------------
__device__ __forceinline__ int block_incl_scan(int x, int tid, int* ws) {
    int lane = tid & 31, wid = tid >> 5;
    #pragma unroll
    for (int o = 1; o < 32; o <<= 1) {
        int y = __shfl_up_sync(0xffffffffu, x, o);
        if (lane >= o) x += y;
    }
    if (lane == 31) ws[wid] = x;
    __syncthreads();
    if (wid == 0) {
        int v = (lane < 8) ? ws[lane] : 0;
        #pragma unroll
        for (int o = 1; o < 8; o <<= 1) {
            int y = __shfl_up_sync(0xffffffffu, v, o);
            if (lane >= o) v += y;
        }
        if (lane < 8) ws[lane] = v;
    }
    __syncthreads();
    if (wid > 0) x += ws[wid - 1];
    return x;
}

// scan1: per-block sums of 1024-count chunks
__global__ __launch_bounds__(256) void scan1_kernel(int V) {
    __shared__ int ws[8];
    int g = blockIdx.y, b = blockIdx.x, tid = threadIdx.x;
    int base = b * 1024 + tid * 4;
    int s = 0;
    #pragma unroll
    for (int j = 0; j < 4; j++) {
        int i = base + j;
        if (i < V) s += g_cnt[g * V_MAX + i];
    }
    int incl = block_incl_scan(s, tid, ws);
    if (tid == 255) g_bsum[g * NBMAX + b] = incl;   // block total
}

// scan2: scan block sums (128 per graph), write off[V]
__global__ __launch_bounds__(128) void scan2_kernel(int V) {
    __shared__ int ws[8];
    int g = blockIdx.x, t = threadIdx.x;
    int x = g_bsum[g * NBMAX + t];
    int orig = x;
    int incl = block_incl_scan(x, t, ws);
    g_bsum[g * NBMAX + t] = incl - orig;            // exclusive block offset
    if (t == 127) g_off[g * (V_MAX + 1) + V] = incl; // grand total
}

// scan3: write per-node offsets + cursors
__global__ __launch_bounds__(256) void scan3_kernel(int V) {
    __shared__ int ws[8];
    int g = blockIdx.y, b = blockIdx.x, tid = threadIdx.x;
    int base = b * 1024 + tid * 4;
    int c[4];
    int s = 0;
    #pragma unroll
    for (int j = 0; j < 4; j++) {
        int i = base + j;
        c[j] = (i < V) ? g_cnt[g * V_MAX + i] : 0;
        s += c[j];
    }
    int incl = block_incl_scan(s, tid, ws);
    int p = g_bsum[g * NBMAX + b] + incl - s;       // exclusive thread offset
    #pragma unroll
    for (int j = 0; j < 4; j++) {
        int i = base + j;
        if (i < V) {
            g_off[g * (V_MAX + 1) + i] = p;
            g_cur[g * V_MAX + i] = p;
            p += c[j];
        }
    }
}

// ---------------- scatter payloads into dst-sorted bins ------------------------
__global__ __launch_bounds__(256) void scatter_kernel(
    const int* __restrict__ dst, const int* __restrict__ src, int E, int g,
    int* __restrict__ bin)
{
    int i = blockIdx.x * blockDim.x + threadIdx.x;
    if (i >= E) return;
    int d = dst[i];
    int p = atomicAdd(&g_cur[g * V_MAX + d], 1);
    bin[p] = src ? src[i] : i;
}

// ---------------- scores + pre-scale: w=exp(tanh(N@W1)@w2), WN = w*N ----------
__device__ __forceinline__ void score_scale_4nodes(
    const float* __restrict__ N, const float* __restrict__ sW,
    const float* __restrict__ sw2, float* __restrict__ wOut,
    float* __restrict__ WN, int base, int V, int lane)
{
    float n0[4], n1[4];
    #pragma unroll
    for (int i = 0; i < 4; i++) {
        int v = (base + i < V) ? base + i : V - 1;
        n0[i] = N[v * D + lane];
        n1[i] = N[v * D + 32 + lane];
    }
    float a0[4] = {0.f,0.f,0.f,0.f}, a1[4] = {0.f,0.f,0.f,0.f};
    #pragma unroll
    for (int k = 0; k < 32; k++) {
        float w0 = sW[k * D + lane], w1 = sW[k * D + 32 + lane];
        #pragma unroll
        for (int i = 0; i < 4; i++) {
            float nk = __shfl_sync(0xffffffffu, n0[i], k);
            a0[i] += nk * w0; a1[i] += nk * w1;
        }
    }
    #pragma unroll
    for (int k = 0; k < 32; k++) {
        float w0 = sW[(k + 32) * D + lane], w1 = sW[(k + 32) * D + 32 + lane];
        #pragma unroll
        for (int i = 0; i < 4; i++) {
            float nk = __shfl_sync(0xffffffffu, n1[i], k);
            a0[i] += nk * w0; a1[i] += nk * w1;
        }
    }
    #pragma unroll
    for (int i = 0; i < 4; i++) {
        float e = tanhf(a0[i]) * sw2[lane] + tanhf(a1[i]) * sw2[32 + lane];
        #pragma unroll
        for (int o = 16; o > 0; o >>= 1) e += __shfl_xor_sync(0xffffffffu, e, o);
        float w = expf(e);
        int v = base + i;
        if (v < V) {
            if (lane == 0) wOut[v] = w;
            WN[v * D + lane]      = w * n0[i];
            WN[v * D + 32 + lane] = w * n1[i];
        }
    }
}

__global__ __launch_bounds__(256) void scores_kernel(
    const float* __restrict__ localN, const float* __restrict__ globalN,
    const float* __restrict__ lW1, const float* __restrict__ lw2,
    const float* __restrict__ gW1, const float* __restrict__ gw2, int V)
{
    __shared__ float sWl[D * D];
    __shared__ float sWg[D * D];
    __shared__ float swl[D];
    __shared__ float swg[D];
    for (int i = threadIdx.x; i < D * D; i += blockDim.x) { sWl[i] = lW1[i]; sWg[i] = gW1[i]; }
    for (int i = threadIdx.x; i < D; i += blockDim.x)     { swl[i] = lw2[i]; swg[i] = gw2[i]; }
    __syncthreads();

    int lane = threadIdx.x & 31;
    int grp  = (blockIdx.x * blockDim.x + threadIdx.x) >> 5;
    int ngrp = (gridDim.x * blockDim.x) >> 5;

    for (int base = grp * 4; base < V; base += ngrp * 4) {
        score_scale_4nodes(localN,  sWl, swl, g_wL, g_WNL, base, V, lane);
        score_scale_4nodes(globalN, sWg, swg, g_wG, g_WNG, base, V, lane);
    }
}

// ---------------- GAT gather: one warp per node, normalized write -------------
__global__ __launch_bounds__(256) void gat_gather_kernel(
    const int* __restrict__ off, const int* __restrict__ bin,
    const float* __restrict__ WN, const float* __restrict__ w,
    float* __restrict__ outBase, int stride, int V)
{
    int warp = (blockIdx.x * blockDim.x + threadIdx.x) >> 5;
    int lane = threadIdx.x & 31;
    if (warp >= V) return;
    int e = off[warp], eEnd = off[warp + 1];
    const float2* WN2 = (const float2*)WN;
    float ax = 0.f, ay = 0.f, den = 0.f;
    for (; e + 2 <= eEnd; e += 2) {
        int s0 = bin[e], s1 = bin[e + 1];
        float2 x0 = WN2[(size_t)s0 * 32 + lane];
        float2 x1 = WN2[(size_t)s1 * 32 + lane];
        float w0 = __ldg(w + s0), w1 = __ldg(w + s1);
        ax += x0.x + x1.x; ay += x0.y + x1.y; den += w0 + w1;
    }
    if (e < eEnd) {
        int s = bin[e];
        float2 x = WN2[(size_t)s * 32 + lane];
        ax += x.x; ay += x.y; den += __ldg(w + s);
    }
    float inv = den > 0.f ? 1.f / den : 1.f;
    float2* o = (float2*)(outBase + (size_t)warp * stride);
    o[lane] = make_float2(ax * inv, ay * inv);
}

// ---------------- mean gather: one warp per node, normalized write ------------
__global__ __launch_bounds__(256) void mean_gather_kernel(
    const int* __restrict__ off, const int* __restrict__ bin,
    const float* __restrict__ Edata, float* __restrict__ Y, int V)
{
    int warp = (blockIdx.x * blockDim.x + threadIdx.x) >> 5;
    int lane = threadIdx.x & 31;
    if (warp >= V) return;
    int e = off[warp], eEnd = off[warp + 1];
    int cnt = eEnd - e;
    const float2* E2 = (const float2*)Edata;
    float ax = 0.f, ay = 0.f;
    for (; e + 2 <= eEnd; e += 2) {
        int b0 = bin[e], b1 = bin[e + 1];
        float2 x0 = E2[(size_t)b0 * 32 + lane];
        float2 x1 = E2[(size_t)b1 * 32 + lane];
        ax += x0.x + x1.x; ay += x0.y + x1.y;
    }
    if (e < eEnd) {
        int b0 = bin[e];
        float2 x = E2[(size_t)b0 * 32 + lane];
        ax += x.x; ay += x.y;
    }
    float inv = cnt > 0 ? 1.f / (float)cnt : 1.f;
    float2* o = (float2*)(Y + (size_t)warp * D);
    o[lane] = make_float2(ax * inv, ay * inv);
}

// ---------------- finalize: attention over YI/YS, S, write out[:,64:128] ------
__global__ __launch_bounds__(256) void finalize_kernel(
    float* __restrict__ out, const float* __restrict__ Ws,
    const float* __restrict__ eW1, const float* __restrict__ ew2,
    const float* __restrict__ eW3, int V)
{
    __shared__ float sW1[D * D];
    __shared__ float sW3[D * D];
    __shared__ float sw2[D];
    for (int i = threadIdx.x; i < D * D; i += blockDim.x) { sW1[i] = eW1[i]; sW3[i] = eW3[i]; }
    for (int i = threadIdx.x; i < D; i += blockDim.x)     { sw2[i] = ew2[i]; }
    __syncthreads();

    int lane = threadIdx.x & 31;
    int grp  = (blockIdx.x * blockDim.x + threadIdx.x) >> 5;
    int ngrp = (gridDim.x * blockDim.x) >> 5;

    for (int base = grp * 2; base < V; base += ngrp * 2) {
        float yi0[2], yi1[2], ys0[2], ys1[2];
        #pragma unroll
        for (int i = 0; i < 2; i++) {
            int v = (base + i < V) ? base + i : V - 1;
            yi0[i] = g_YI[v * D + lane];
            yi1[i] = g_YI[v * D + 32 + lane];
            ys0[i] = g_YS[v * D + lane];
            ys1[i] = g_YS[v * D + 32 + lane];
        }

        float a0[2] = {0.f,0.f}, a1[2] = {0.f,0.f};
        float b0[2] = {0.f,0.f}, b1[2] = {0.f,0.f};
        #pragma unroll
        for (int k = 0; k < 32; k++) {
            float w0 = sW1[k * D + lane], w1 = sW1[k * D + 32 + lane];
            #pragma unroll
            for (int i = 0; i < 2; i++) {
                float yik = __shfl_sync(0xffffffffu, yi0[i], k);
                float ysk = __shfl_sync(0xffffffffu, ys0[i], k);
                a0[i] += yik * w0; a1[i] += yik * w1;
                b0[i] += ysk * w0; b1[i] += ysk * w1;
            }
        }
        #pragma unroll
        for (int k = 0; k < 32; k++) {
            float w0 = sW1[(32 + k) * D + lane], w1 = sW1[(32 + k) * D + 32 + lane];
            #pragma unroll
            for (int i = 0; i < 2; i++) {
                float yik = __shfl_sync(0xffffffffu, yi1[i], k);
                float ysk = __shfl_sync(0xffffffffu, ys1[i], k);
                a0[i] += yik * w0; a1[i] += yik * w1;
                b0[i] += ysk * w0; b1[i] += ysk * w1;
            }
        }

        float oy0[2], oy1[2];
        #pragma unroll
        for (int i = 0; i < 2; i++) {
            float eI = tanhf(a0[i]) * sw2[lane] + tanhf(a1[i]) * sw2[32 + lane];
            float eS = tanhf(b0[i]) * sw2[lane] + tanhf(b1[i]) * sw2[32 + lane];
            #pragma unroll
            for (int o = 16; o > 0; o >>= 1) {
                eI += __shfl_xor_sync(0xffffffffu, eI, o);
                eS += __shfl_xor_sync(0xffffffffu, eS, o);
            }
            float mx = fmaxf(eI, eS);
            float u0 = expf(eI - mx), u1 = expf(eS - mx);
            float inv = 1.f / (u0 + u1);
            oy0[i] = u0 * inv * yi0[i] + u1 * inv * ys0[i];
            oy1[i] = u0 * inv * yi1[i] + u1 * inv * ys1[i];
        }

        float f0[2] = {0.f,0.f}, f1[2] = {0.f,0.f};
        #pragma unroll
        for (int k = 0; k < 32; k++) {
            float w0 = sW3[k * D + lane], w1 = sW3[k * D + 32 + lane];
            #pragma unroll
            for (int i = 0; i < 2; i++) {
                float ok = __shfl_sync(0xffffffffu, oy0[i], k);
                f0[i] += ok * w0; f1[i] += ok * w1;
            }
        }
        #pragma unroll
        for (int k = 0; k < 32; k++) {
            float w0 = sW3[(32 + k) * D + lane], w1 = sW3[(32 + k) * D + 32 + lane];
            #pragma unroll
            for (int i = 0; i < 2; i++) {
                float ok = __shfl_sync(0xffffffffu, oy1[i], k);
                f0[i] += ok * w0; f1[i] += ok * w1;
            }
        }

        #pragma unroll
        for (int i = 0; i < 2; i++) {
            int v = base + i;
            if (v >= V) break;
            float np0 = g_Np[v * D + lane];
            float np1 = g_Np[v * D + 32 + lane];
            out[v * 128 + 64 + lane] = Ws[v * D + lane]      * f0[i] + np0;
            out[v * 128 + 96 + lane] = Ws[v * D + 32 + lane] * f1[i] + np1;
        }
    }
}

// ---------------- launch ------------------------------------------------------
extern "C" void kernel_launch(void* const* d_in, const int* in_sizes, int n_in,
                              void* d_out, int out_size)
{
    const float* local_N  = (const float*)d_in[0];
    const float* global_N = (const float*)d_in[1];
    const float* edge_E   = (const float*)d_in[2];
    const float* Ws       = (const float*)d_in[3];
    const float* lW1      = (const float*)d_in[4];
    const float* lw2      = (const float*)d_in[5];
    const float* gW1      = (const float*)d_in[6];
    const float* gw2      = (const float*)d_in[7];
    const float* eW1      = (const float*)d_in[8];
    const float* ew2      = (const float*)d_in[9];
    const float* eW3      = (const float*)d_in[10];
    const int* ng_src     = (const int*)d_in[11];
    const int* ng_dst     = (const int*)d_in[12];
    const int* local_src  = (const int*)d_in[13];
    const int* local_dst  = (const int*)d_in[14];
    const int* int_dst    = (const int*)d_in[16];
    const int* sim_dst    = (const int*)d_in[18];

    const int V      = in_sizes[0] / D;
    const int E_NG   = in_sizes[11];
    const int E_LOC  = in_sizes[13];
    const int E_INT  = in_sizes[15];
    const int E_SIM  = in_sizes[17];

    float* out = (float*)d_out;

    float *pWL, *pWG, *pWNL, *pWNG, *pNp, *pYI, *pYS;
    int *pOff, *pBinNG, *pBinLOC, *pBinI, *pBinS;
    cudaGetSymbolAddress((void**)&pWL,  g_wL);
    cudaGetSymbolAddress((void**)&pWG,  g_wG);
    cudaGetSymbolAddress((void**)&pWNL, g_WNL);
    cudaGetSymbolAddress((void**)&pWNG, g_WNG);
    cudaGetSymbolAddress((void**)&pNp,  g_Np);
    cudaGetSymbolAddress((void**)&pYI,  g_YI);
    cudaGetSymbolAddress((void**)&pYS,  g_YS);
    cudaGetSymbolAddress((void**)&pOff, g_off);
    cudaGetSymbolAddress((void**)&pBinNG,  g_binNG);
    cudaGetSymbolAddress((void**)&pBinLOC, g_binLOC);
    cudaGetSymbolAddress((void**)&pBinI,   g_binI);
    cudaGetSymbolAddress((void**)&pBinS,   g_binS);

    // --- binning: counts -> offsets -> scatter ---
    zero_cnt_kernel<<<(4 * V_MAX + 255) / 256, 256>>>();
    count_kernel<<<(E_NG  + 255) / 256, 256>>>(ng_dst,    E_NG,  0);
    count_kernel<<<(E_LOC + 255) / 256, 256>>>(local_dst, E_LOC, 1);
    count_kernel<<<(E_INT + 255) / 256, 256>>>(int_dst,   E_INT, 2);
    count_kernel<<<(E_SIM + 255) / 256, 256>>>(sim_dst,   E_SIM, 3);

    dim3 sgrid(NBMAX, 4);
    scan1_kernel<<<sgrid, 256>>>(V);
    scan2_kernel<<<4, 128>>>(V);
    scan3_kernel<<<sgrid, 256>>>(V);

    scatter_kernel<<<(E_NG  + 255) / 256, 256>>>(ng_dst,    ng_src,    E_NG,  0, pBinNG);
    scatter_kernel<<<(E_LOC + 255) / 256, 256>>>(local_dst, local_src, E_LOC, 1, pBinLOC);
    scatter_kernel<<<(E_INT + 255) / 256, 256>>>(int_dst,   nullptr,   E_INT, 2, pBinI);
    scatter_kernel<<<(E_SIM + 255) / 256, 256>>>(sim_dst,   nullptr,   E_SIM, 3, pBinS);

    // --- node scores + pre-scaled rows (overlaps logically with binning) ---
    scores_kernel<<<(V + 31) / 32, 256>>>(local_N, global_N, lW1, lw2, gW1, gw2, V);

    // --- gathers ---
    int ggrid = (V * 32 + 255) / 256;
    gat_gather_kernel<<<ggrid, 256>>>(pOff + 0 * (V_MAX + 1), pBinNG,  pWNG, pWG, pNp, 64, V);
    gat_gather_kernel<<<ggrid, 256>>>(pOff + 1 * (V_MAX + 1), pBinLOC, pWNL, pWL, out, 128, V);
    mean_gather_kernel<<<ggrid, 256>>>(pOff + 2 * (V_MAX + 1), pBinI, edge_E, pYI, V);
    mean_gather_kernel<<<ggrid, 256>>>(pOff + 3 * (V_MAX + 1), pBinS, edge_E + (size_t)E_INT * D, pYS, V);

    // --- finalize ---
    finalize_kernel<<<(V + 15) / 16, 256>>>(out, Ws, eW1, ew2, eW3, V);
}

// round 4
// speedup vs baseline: 1.4098x; 1.0475x over previous
#include <cuda_runtime.h>
#include <cuda_fp16.h>
#include <math.h>

#define D 64
#define V_MAX 100000
#define NBMAX 128
#define E_NG_MAX  2000000
#define E_LOC_MAX 1000000
#define E_INT_MAX 1200000
#define E_SIM_MAX  800000

// ---------------- scratch ------------------------------------------------------
__device__ float   g_wL[V_MAX];
__device__ float   g_wG[V_MAX];
__device__ __half2 g_WNL[V_MAX * 32];
__device__ __half2 g_WNG[V_MAX * 32];

__device__ int g_cnt[4 * V_MAX];
__device__ int g_off[4 * (V_MAX + 1)];
__device__ int g_cur[4 * V_MAX];
__device__ int g_bsum[4 * NBMAX];
__device__ int g_binNG[E_NG_MAX];
__device__ int g_binLOC[E_LOC_MAX];
__device__ int g_binI[E_INT_MAX];
__device__ int g_binS[E_SIM_MAX];

// ---------------- zero counts ---------------------------------------------------
__global__ void zero_cnt_kernel() {
    int i = blockIdx.x * blockDim.x + threadIdx.x;
    if (i < 4 * V_MAX) g_cnt[i] = 0;
}

// ---------------- fused histogram over 4 graphs ----------------------------------
__global__ __launch_bounds__(256) void count_kernel(
    const int* __restrict__ d0, int e0, const int* __restrict__ d1, int e1,
    const int* __restrict__ d2, int e2, const int* __restrict__ d3, int e3)
{
    int i = blockIdx.x * blockDim.x + threadIdx.x;
    int g, j;
    if (i < e0)                { g = 0; j = i; }
    else if (i < e0 + e1)      { g = 1; j = i - e0; }
    else if (i < e0 + e1 + e2) { g = 2; j = i - e0 - e1; }
    else if (i < e0 + e1 + e2 + e3) { g = 3; j = i - e0 - e1 - e2; }
    else return;
    const int* d = (g == 0) ? d0 : (g == 1) ? d1 : (g == 2) ? d2 : d3;
    atomicAdd(&g_cnt[g * V_MAX + d[j]], 1);
}

// ---------------- scan helpers ----------------------------------------------------
__device__ __forceinline__ int block_incl_scan(int x, int tid, int* ws) {
    int lane = tid & 31, wid = tid >> 5;
    #pragma unroll
    for (int o = 1; o < 32; o <<= 1) {
        int y = __shfl_up_sync(0xffffffffu, x, o);
        if (lane >= o) x += y;
    }
    if (lane == 31) ws[wid] = x;
    __syncthreads();
    if (wid == 0) {
        int v = (lane < 8) ? ws[lane] : 0;
        #pragma unroll
        for (int o = 1; o < 8; o <<= 1) {
            int y = __shfl_up_sync(0xffffffffu, v, o);
            if (lane >= o) v += y;
        }
        if (lane < 8) ws[lane] = v;
    }
    __syncthreads();
    if (wid > 0) x += ws[wid - 1];
    return x;
}

__global__ __launch_bounds__(256) void scan1_kernel(int V) {
    __shared__ int ws[8];
    int g = blockIdx.y, b = blockIdx.x, tid = threadIdx.x;
    int base = b * 1024 + tid * 4;
    int s = 0;
    #pragma unroll
    for (int j = 0; j < 4; j++) { int i = base + j; if (i < V) s += g_cnt[g * V_MAX + i]; }
    int incl = block_incl_scan(s, tid, ws);
    if (tid == 255) g_bsum[g * NBMAX + b] = incl;
}

__global__ __launch_bounds__(128) void scan2_kernel(int V) {
    __shared__ int ws[8];
    int g = blockIdx.x, t = threadIdx.x;
    int x = g_bsum[g * NBMAX + t];
    int orig = x;
    int incl = block_incl_scan(x, t, ws);
    g_bsum[g * NBMAX + t] = incl - orig;
    if (t == 127) g_off[g * (V_MAX + 1) + V] = incl;
}

__global__ __launch_bounds__(256) void scan3_kernel(int V) {
    __shared__ int ws[8];
    int g = blockIdx.y, b = blockIdx.x, tid = threadIdx.x;
    int base = b * 1024 + tid * 4;
    int c[4]; int s = 0;
    #pragma unroll
    for (int j = 0; j < 4; j++) {
        int i = base + j;
        c[j] = (i < V) ? g_cnt[g * V_MAX + i] : 0;
        s += c[j];
    }
    int incl = block_incl_scan(s, tid, ws);
    int p = g_bsum[g * NBMAX + b] + incl - s;
    #pragma unroll
    for (int j = 0; j < 4; j++) {
        int i = base + j;
        if (i < V) { g_off[g * (V_MAX + 1) + i] = p; g_cur[g * V_MAX + i] = p; p += c[j]; }
    }
}

// ---------------- fused scatter over 4 graphs --------------------------------------
__global__ __launch_bounds__(256) void scatter_kernel(
    const int* __restrict__ d0, const int* __restrict__ s0, int e0,
    const int* __restrict__ d1, const int* __restrict__ s1, int e1,
    const int* __restrict__ d2, int e2,
    const int* __restrict__ d3, int e3)
{
    int i = blockIdx.x * blockDim.x + threadIdx.x;
    int g, j;
    if (i < e0)                { g = 0; j = i; }
    else if (i < e0 + e1)      { g = 1; j = i - e0; }
    else if (i < e0 + e1 + e2) { g = 2; j = i - e0 - e1; }
    else if (i < e0 + e1 + e2 + e3) { g = 3; j = i - e0 - e1 - e2; }
    else return;
    int dst, payload; int* bin;
    if (g == 0)      { dst = d0[j]; payload = s0[j]; bin = g_binNG; }
    else if (g == 1) { dst = d1[j]; payload = s1[j]; bin = g_binLOC; }
    else if (g == 2) { dst = d2[j]; payload = j;     bin = g_binI; }
    else             { dst = d3[j]; payload = j;     bin = g_binS; }
    int p = atomicAdd(&g_cur[g * V_MAX + dst], 1);
    bin[p] = payload;
}

// ---------------- scores + pre-scale (interleaved float2 layout) -------------------
__device__ __forceinline__ void score4(
    const float2* __restrict__ N2, const float* __restrict__ sW,
    const float2* __restrict__ sw2, float* __restrict__ wOut,
    __half2* __restrict__ WN, int base, int V, int lane)
{
    float2 n[4];
    #pragma unroll
    for (int i = 0; i < 4; i++) {
        int v = (base + i < V) ? base + i : V - 1;
        n[i] = N2[(size_t)v * 32 + lane];
    }
    float2 a[4] = {{0,0},{0,0},{0,0},{0,0}};
    const float2* W2 = (const float2*)sW;
    #pragma unroll
    for (int kk = 0; kk < 32; kk++) {
        float2 w0 = W2[(2 * kk) * 32 + lane];
        float2 w1 = W2[(2 * kk + 1) * 32 + lane];
        #pragma unroll
        for (int i = 0; i < 4; i++) {
            float xk0 = __shfl_sync(0xffffffffu, n[i].x, kk);
            float xk1 = __shfl_sync(0xffffffffu, n[i].y, kk);
            a[i].x += xk0 * w0.x + xk1 * w1.x;
            a[i].y += xk0 * w0.y + xk1 * w1.y;
        }
    }
    float2 w2v = sw2[lane];
    #pragma unroll
    for (int i = 0; i < 4; i++) {
        float e = tanhf(a[i].x) * w2v.x + tanhf(a[i].y) * w2v.y;
        #pragma unroll
        for (int o = 16; o > 0; o >>= 1) e += __shfl_xor_sync(0xffffffffu, e, o);
        float w = expf(e);
        int v = base + i;
        if (v < V) {
            if (lane == 0) wOut[v] = w;
            WN[(size_t)v * 32 + lane] = __float22half2_rn(make_float2(w * n[i].x, w * n[i].y));
        }
    }
}

__global__ __launch_bounds__(256) void scores_kernel(
    const float* __restrict__ localN, const float* __restrict__ globalN,
    const float* __restrict__ lW1, const float* __restrict__ lw2,
    const float* __restrict__ gW1, const float* __restrict__ gw2, int V)
{
    __shared__ float sWl[D * D];
    __shared__ float sWg[D * D];
    __shared__ float2 swl[32];
    __shared__ float2 swg[32];
    for (int i = threadIdx.x; i < D * D; i += blockDim.x) { sWl[i] = lW1[i]; sWg[i] = gW1[i]; }
    for (int i = threadIdx.x; i < 32; i += blockDim.x) {
        swl[i] = ((const float2*)lw2)[i];
        swg[i] = ((const float2*)gw2)[i];
    }
    __syncthreads();

    int lane = threadIdx.x & 31;
    int grp  = (blockIdx.x * blockDim.x + threadIdx.x) >> 5;
    int ngrp = (gridDim.x * blockDim.x) >> 5;

    for (int base = grp * 4; base < V; base += ngrp * 4) {
        score4((const float2*)localN,  sWl, swl, g_wL, g_WNL, base, V, lane);
        score4((const float2*)globalN, sWg, swg, g_wG, g_WNG, base, V, lane);
    }
}

// ---------------- gather helpers ----------------------------------------------------
__device__ __forceinline__ void gat_gather(
    const int* __restrict__ bin, int e, int eEnd,
    const __half2* __restrict__ WN, const float* __restrict__ w,
    int lane, float2& acc)
{
    float ax = 0.f, ay = 0.f, den = 0.f;
    for (; e + 2 <= eEnd; e += 2) {
        int s0 = bin[e], s1 = bin[e + 1];
        float2 x0 = __half22float2(WN[(size_t)s0 * 32 + lane]);
        float2 x1 = __half22float2(WN[(size_t)s1 * 32 + lane]);
        float w0 = __ldg(w + s0), w1 = __ldg(w + s1);
        ax += x0.x + x1.x; ay += x0.y + x1.y; den += w0 + w1;
    }
    if (e < eEnd) {
        int s = bin[e];
        float2 x = __half22float2(WN[(size_t)s * 32 + lane]);
        ax += x.x; ay += x.y; den += __ldg(w + s);
    }
    float inv = den > 0.f ? 1.f / den : 1.f;
    acc = make_float2(ax * inv, ay * inv);
}

__device__ __forceinline__ void mean_gather(
    const int* __restrict__ bin, int e, int eEnd,
    const float2* __restrict__ E2, int lane, float2& acc)
{
    int cnt = eEnd - e;
    float ax = 0.f, ay = 0.f;
    for (; e + 2 <= eEnd; e += 2) {
        int b0 = bin[e], b1 = bin[e + 1];
        float2 x0 = E2[(size_t)b0 * 32 + lane];
        float2 x1 = E2[(size_t)b1 * 32 + lane];
        ax += x0.x + x1.x; ay += x0.y + x1.y;
    }
    if (e < eEnd) {
        int b0 = bin[e];
        float2 x = E2[(size_t)b0 * 32 + lane];
        ax += x.x; ay += x.y;
    }
    float inv = cnt > 0 ? 1.f / (float)cnt : 1.f;
    acc = make_float2(ax * inv, ay * inv);
}

// ---------------- mega node kernel: all gathers + attention + output ----------------
__global__ __launch_bounds__(256) void node_kernel(
    float* __restrict__ out, const float* __restrict__ edge_E, int E_INT,
    const float* __restrict__ Ws,
    const float* __restrict__ eW1, const float* __restrict__ ew2,
    const float* __restrict__ eW3, int V)
{
    __shared__ float sW1[D * D];
    __shared__ float sW3[D * D];
    __shared__ float2 sw2[32];
    for (int i = threadIdx.x; i < D * D; i += blockDim.x) { sW1[i] = eW1[i]; sW3[i] = eW3[i]; }
    for (int i = threadIdx.x; i < 32; i += blockDim.x) sw2[i] = ((const float2*)ew2)[i];
    __syncthreads();

    int v    = (blockIdx.x * blockDim.x + threadIdx.x) >> 5;
    int lane = threadIdx.x & 31;
    if (v >= V) return;

    const int* offNG  = g_off + 0 * (V_MAX + 1);
    const int* offLOC = g_off + 1 * (V_MAX + 1);
    const int* offI   = g_off + 2 * (V_MAX + 1);
    const int* offS   = g_off + 3 * (V_MAX + 1);

    float2* out2 = (float2*)out;

    // local GAT -> out[:, 0:64]
    {
        float2 lacc;
        gat_gather(g_binLOC, offLOC[v], offLOC[v + 1], g_WNL, g_wL, lane, lacc);
        out2[(size_t)v * 64 + lane] = lacc;
    }

    // ng GAT
    float2 np;
    gat_gather(g_binNG, offNG[v], offNG[v + 1], g_WNG, g_wG, lane, np);

    // means
    float2 yi, ys;
    mean_gather(g_binI, offI[v], offI[v + 1], (const float2*)edge_E, lane, yi);
    mean_gather(g_binS, offS[v], offS[v + 1],
                (const float2*)(edge_E + (size_t)E_INT * D), lane, ys);

    // a = yi @ eW1, b = ys @ eW1 (interleaved)
    float2 a = make_float2(0.f, 0.f), b = make_float2(0.f, 0.f);
    const float2* W1_2 = (const float2*)sW1;
    #pragma unroll
    for (int kk = 0; kk < 32; kk++) {
        float2 w0 = W1_2[(2 * kk) * 32 + lane];
        float2 w1 = W1_2[(2 * kk + 1) * 32 + lane];
        float yi0 = __shfl_sync(0xffffffffu, yi.x, kk);
        float yi1 = __shfl_sync(0xffffffffu, yi.y, kk);
        float ys0 = __shfl_sync(0xffffffffu, ys.x, kk);
        float ys1 = __shfl_sync(0xffffffffu, ys.y, kk);
        a.x += yi0 * w0.x + yi1 * w1.x;
        a.y += yi0 * w0.y + yi1 * w1.y;
        b.x += ys0 * w0.x + ys1 * w1.x;
        b.y += ys0 * w0.y + ys1 * w1.y;
    }
    float2 w2v = sw2[lane];
    float eI = tanhf(a.x) * w2v.x + tanhf(a.y) * w2v.y;
    float eS = tanhf(b.x) * w2v.x + tanhf(b.y) * w2v.y;
    #pragma unroll
    for (int o = 16; o > 0; o >>= 1) {
        eI += __shfl_xor_sync(0xffffffffu, eI, o);
        eS += __shfl_xor_sync(0xffffffffu, eS, o);
    }
    float mx = fmaxf(eI, eS);
    float u0 = expf(eI - mx), u1 = expf(eS - mx);
    float inv = 1.f / (u0 + u1);
    float A0 = u0 * inv, A1 = u1 * inv;
    float2 oy = make_float2(A0 * yi.x + A1 * ys.x, A0 * yi.y + A1 * ys.y);

    // Fg = oy @ eW3
    float2 f = make_float2(0.f, 0.f);
    const float2* W3_2 = (const float2*)sW3;
    #pragma unroll
    for (int kk = 0; kk < 32; kk++) {
        float2 w0 = W3_2[(2 * kk) * 32 + lane];
        float2 w1 = W3_2[(2 * kk + 1) * 32 + lane];
        float o0 = __shfl_sync(0xffffffffu, oy.x, kk);
        float o1 = __shfl_sync(0xffffffffu, oy.y, kk);
        f.x += o0 * w0.x + o1 * w1.x;
        f.y += o0 * w0.y + o1 * w1.y;
    }

    float2 wsv = ((const float2*)Ws)[(size_t)v * 32 + lane];
    out2[(size_t)v * 64 + 32 + lane] = make_float2(wsv.x * f.x + np.x, wsv.y * f.y + np.y);
}

// ---------------- launch ---------------------------------------------------------
extern "C" void kernel_launch(void* const* d_in, const int* in_sizes, int n_in,
                              void* d_out, int out_size)
{
    const float* local_N  = (const float*)d_in[0];
    const float* global_N = (const float*)d_in[1];
    const float* edge_E   = (const float*)d_in[2];
    const float* Ws       = (const float*)d_in[3];
    const float* lW1      = (const float*)d_in[4];
    const float* lw2      = (const float*)d_in[5];
    const float* gW1      = (const float*)d_in[6];
    const float* gw2      = (const float*)d_in[7];
    const float* eW1      = (const float*)d_in[8];
    const float* ew2      = (const float*)d_in[9];
    const float* eW3      = (const float*)d_in[10];
    const int* ng_src     = (const int*)d_in[11];
    const int* ng_dst     = (const int*)d_in[12];
    const int* local_src  = (const int*)d_in[13];
    const int* local_dst  = (const int*)d_in[14];
    const int* int_dst    = (const int*)d_in[16];
    const int* sim_dst    = (const int*)d_in[18];

    const int V      = in_sizes[0] / D;
    const int E_NG   = in_sizes[11];
    const int E_LOC  = in_sizes[13];
    const int E_INT  = in_sizes[15];
    const int E_SIM  = in_sizes[17];
    const int E_ALL  = E_NG + E_LOC + E_INT + E_SIM;

    float* out = (float*)d_out;

    // --- binning ---
    zero_cnt_kernel<<<(4 * V_MAX + 255) / 256, 256>>>();
    count_kernel<<<(E_ALL + 255) / 256, 256>>>(ng_dst, E_NG, local_dst, E_LOC,
                                               int_dst, E_INT, sim_dst, E_SIM);
    dim3 sgrid(NBMAX, 4);
    scan1_kernel<<<sgrid, 256>>>(V);
    scan2_kernel<<<4, 128>>>(V);
    scan3_kernel<<<sgrid, 256>>>(V);
    scatter_kernel<<<(E_ALL + 255) / 256, 256>>>(ng_dst, ng_src, E_NG,
                                                 local_dst, local_src, E_LOC,
                                                 int_dst, E_INT, sim_dst, E_SIM);

    // --- node scores + fp16 pre-scaled rows ---
    scores_kernel<<<(V + 31) / 32, 256>>>(local_N, global_N, lW1, lw2, gW1, gw2, V);

    // --- fused per-node gathers + attention + output ---
    node_kernel<<<(V * 32 + 255) / 256, 256>>>(out, edge_E, E_INT, Ws, eW1, ew2, eW3, V);
}